// round 1
// baseline (speedup 1.0000x reference)
#include <cuda_runtime.h>

#define HW 256
#define PS 113   // (256-32)/2 + 1

// smem layout (dynamic):
//   q      : 128*256 floats  (pair-row sums of prob0)      131072 B
//   csrow  : 2*256 floats    (double-buffered colsum row)     2048 B
//   redMax : 8 u64                                              64 B
//   redMin : 8 u64                                              64 B
//   rects  : 8 int                                              32 B
#define SMEM_BYTES (131072 + 2048 + 64 + 64 + 32)

extern "C" __global__ void __launch_bounds__(256, 1)
genmask_kernel(const float* __restrict__ infeat, float* __restrict__ out, int mask_off)
{
    extern __shared__ float smem[];
    float* q     = smem;                       // [128][256]
    float* csrow = smem + 128 * HW;            // [2][256]
    unsigned long long* redMax = (unsigned long long*)(csrow + 2 * HW); // [8]
    unsigned long long* redMin = redMax + 8;                            // [8]
    int* rects = (int*)(redMin + 8);                                    // [8]

    const int b   = blockIdx.x;
    const int tid = threadIdx.x;

    const float* base0 = infeat + (size_t)b * 2 * HW * HW;   // channel 0
    const float* base1 = base0 + HW * HW;                    // channel 1

    // ---- Phase 1: prob0 = sigmoid(in0 - in1); store pair-row sums q[j][x] ----
    #pragma unroll 4
    for (int j = 0; j < 128; j++) {
        const int y = 2 * j;
        const float a0 = base0[(size_t)y * HW + tid];
        const float a1 = base1[(size_t)y * HW + tid];
        const float b0 = base0[(size_t)(y + 1) * HW + tid];
        const float b1 = base1[(size_t)(y + 1) * HW + tid];
        const float p0 = __fdividef(1.0f, 1.0f + __expf(a1 - a0));
        const float p1 = __fdividef(1.0f, 1.0f + __expf(b1 - b0));
        q[j * HW + tid] = p0 + p1;
    }
    __syncthreads();

    // ---- Phase 2: vertical sliding sum (over 16 pair-rows) + horizontal 32-window ----
    float cs = 0.0f;
    #pragma unroll
    for (int j = 0; j < 16; j++) cs += q[j * HW + tid];

    float bestMax = -1.0f;       // window sums are strictly positive
    float bestMin = 1e30f;
    int   idxMax  = 0, idxMin = 0;

    for (int yo = 0; yo < PS; yo++) {
        float* buf = csrow + (yo & 1) * HW;
        buf[tid] = cs;
        __syncthreads();
        if (tid < PS) {
            // H = sum of csrow[2*tid .. 2*tid+31] (8-byte aligned float2 loads)
            const float2* c2 = (const float2*)buf + tid;
            float h = 0.0f;
            #pragma unroll
            for (int i = 0; i < 16; i++) { float2 v = c2[i]; h += v.x; h += v.y; }
            const int fidx = yo * PS + tid;
            if (h > bestMax) { bestMax = h; idxMax = fidx; }  // strict -> first index kept
            if (h < bestMin) { bestMin = h; idxMin = fidx; }
        }
        if (yo < PS - 1) cs += q[(yo + 16) * HW + tid] - q[yo * HW + tid];
        // no second barrier: double-buffered csrow; next iter's barrier orders reuse
    }

    // ---- Arg reduction: max(H, tie->min idx) and min(H, tie->min idx) ----
    unsigned long long kMax, kMin;
    if (tid < PS) {
        kMax = ((unsigned long long)__float_as_uint(bestMax) << 32)
             | (unsigned long long)(0xFFFFFFFFu - (unsigned)idxMax);
        kMin = ((unsigned long long)__float_as_uint(bestMin) << 32)
             | (unsigned long long)(unsigned)idxMin;
    } else {
        kMax = 0ull;
        kMin = ~0ull;
    }
    #pragma unroll
    for (int o = 16; o > 0; o >>= 1) {
        unsigned long long v;
        v = __shfl_xor_sync(0xFFFFFFFFu, kMax, o); if (v > kMax) kMax = v;
        v = __shfl_xor_sync(0xFFFFFFFFu, kMin, o); if (v < kMin) kMin = v;
    }
    const int warp = tid >> 5;
    if ((tid & 31) == 0) { redMax[warp] = kMax; redMin[warp] = kMin; }
    __syncthreads();

    if (tid == 0) {
        kMax = redMax[0]; kMin = redMin[0];
        #pragma unroll
        for (int w = 1; w < 8; w++) {
            if (redMax[w] > kMax) kMax = redMax[w];
            if (redMin[w] < kMin) kMin = redMin[w];
        }
        const int i0 = (int)(0xFFFFFFFFu - (unsigned)(kMax & 0xFFFFFFFFull)); // class 0
        const int i1 = (int)(kMin & 0xFFFFFFFFull);                           // class 1
        const int px0 = i0 % PS, py0 = i0 / PS;
        const int px1 = i1 % PS, py1 = i1 / PS;
        int r[8] = { 2 * px0, 2 * px0 + 31, 2 * py0, 2 * py0 + 31,
                     2 * px1, 2 * px1 + 31, 2 * py1, 2 * py1 + 31 };
        float* oxy = out + (size_t)b * 8;
        #pragma unroll
        for (int i = 0; i < 8; i++) { oxy[i] = (float)r[i]; rects[i] = r[i]; }
    }
    __syncthreads();

    // ---- Phase 3: mask = union of the two rects (coalesced float4 stores) ----
    const int ox0a = rects[0], ox1a = rects[1], oy0a = rects[2], oy1a = rects[3];
    const int ox0b = rects[4], ox1b = rects[5], oy0b = rects[6], oy1b = rects[7];

    float* mout = out + (size_t)mask_off + (size_t)b * HW * HW;
    const int lane64 = tid & 63;     // x-quad index
    const int rsub   = tid >> 6;     // 0..3 (row within group of 4)
    #pragma unroll 2
    for (int it = 0; it < 64; it++) {
        const int row = it * 4 + rsub;
        const bool iny0 = (row >= oy0a) && (row <= oy1a);
        const bool iny1 = (row >= oy0b) && (row <= oy1b);
        const int x0 = lane64 * 4;
        float va[4];
        #pragma unroll
        for (int kk = 0; kk < 4; kk++) {
            const int xx = x0 + kk;
            const bool m = (iny0 && xx >= ox0a && xx <= ox1a) ||
                           (iny1 && xx >= ox0b && xx <= ox1b);
            va[kk] = m ? 1.0f : 0.0f;
        }
        float4 v; v.x = va[0]; v.y = va[1]; v.z = va[2]; v.w = va[3];
        ((float4*)mout)[row * (HW / 4) + lane64] = v;
    }
}

extern "C" void kernel_launch(void* const* d_in, const int* in_sizes, int n_in,
                              void* d_out, int out_size)
{
    const float* infeat = (const float*)d_in[0];
    const int B = in_sizes[0] / (2 * HW * HW);          // 128
    const int mask_off = out_size - B * HW * HW;         // oxy occupies the front (B*8)

    cudaFuncSetAttribute(genmask_kernel,
                         cudaFuncAttributeMaxDynamicSharedMemorySize, SMEM_BYTES);
    genmask_kernel<<<B, 256, SMEM_BYTES>>>(infeat, (float*)d_out, mask_off);
}

// round 6
// speedup vs baseline: 1.7042x; 1.7042x over previous
#include <cuda_runtime.h>

#define HW   256
#define PS   113      // (256-32)/2 + 1
#define QS   257      // padded row stride for P (prefix) table
#define PRS  129      // padded row stride for pr table
#define RED_OFF (128 * QS + 113 * PRS)

// smem layout (dynamic, floats):
//   P      : 128*257   (vertical prefix of pair-row sums, padded)
//   pr     : 113*129   (pair-column sums of colsum, padded)
//   redMaxHi/Lo, redMinHi/Lo : 8 u32 each  (no 64-bit smem ops anywhere)
//   rects  : 8 int
#define SMEM_FLOATS (RED_OFF + 8 * 4 + 8)
#define SMEM_BYTES  (SMEM_FLOATS * 4)

extern "C" __global__ void __launch_bounds__(256, 1)
genmask_kernel(const float* __restrict__ infeat, float* __restrict__ out, int mask_off)
{
    extern __shared__ float smem[];
    float* P  = smem;                                   // [128][QS]
    float* pr = smem + 128 * QS;                        // [113][PRS]
    unsigned* redMaxHi = (unsigned*)(smem + RED_OFF);   // [8]
    unsigned* redMaxLo = redMaxHi + 8;                  // [8]
    unsigned* redMinHi = redMaxLo + 8;                  // [8]
    unsigned* redMinLo = redMinHi + 8;                  // [8]
    int*      rects    = (int*)(redMinLo + 8);          // [8]

    const int b   = blockIdx.x;
    const int tid = threadIdx.x;

    const float* base0 = infeat + (size_t)b * 2 * HW * HW;   // channel 0
    const float* base1 = base0 + HW * HW;                    // channel 1

    // ---- Phase 1: p0 = sigmoid(in0 - in1); store VERTICAL PREFIX of pair-row sums ----
    {
        float running = 0.0f;
        #pragma unroll 8
        for (int j = 0; j < 128; j++) {
            const int y = 2 * j;
            const float a0 = base0[(size_t)y * HW + tid];
            const float a1 = base1[(size_t)y * HW + tid];
            const float b0 = base0[(size_t)(y + 1) * HW + tid];
            const float b1 = base1[(size_t)(y + 1) * HW + tid];
            const float p0 = __fdividef(1.0f, 1.0f + __expf(a1 - a0));
            const float p1 = __fdividef(1.0f, 1.0f + __expf(b1 - b0));
            running += p0 + p1;
            P[j * QS + tid] = running;         // prefix over pair-rows 0..j
        }
    }
    __syncthreads();

    // ---- Phase 2a: pr[yo][pc] = colsum(yo,2pc) + colsum(yo,2pc+1), fully parallel ----
    // colsum(yo,x) = P[yo+15][x] - (yo>0 ? P[yo-1][x] : 0)
    for (int i = tid; i < PS * 128; i += 256) {
        const int yo = i >> 7;
        const int pc = i & 127;
        const int x0 = 2 * pc;
        const float* Phi = P + (yo + 15) * QS + x0;
        float v = Phi[0] + Phi[1];
        if (yo > 0) {
            const float* Plo = P + (yo - 1) * QS + x0;
            v -= Plo[0] + Plo[1];
        }
        pr[yo * PRS + pc] = v;
    }
    __syncthreads();

    // ---- Phase 2b: per-(row,half) incremental horizontal slide, no barriers ----
    float bestMax = -1.0f;
    float bestMin = 1e30f;
    int   idxMax  = 0, idxMin = 0;

    if (tid < 226) {
        int row, px0, cnt;
        if (tid < PS) { row = tid;       px0 = 0;  cnt = 57; }
        else          { row = tid - PS;  px0 = 57; cnt = 56; }
        const float* prr = pr + row * PRS;

        float H = 0.0f;
        #pragma unroll
        for (int i = 0; i < 16; i++) H += prr[px0 + i];   // window [px0 .. px0+15]

        for (int s = 0; s < cnt; s++) {
            const int px   = px0 + s;
            const int fidx = row * PS + px;
            if (H > bestMax) { bestMax = H; idxMax = fidx; }  // strict -> first index
            if (H < bestMin) { bestMin = H; idxMin = fidx; }
            if (s + 1 < cnt) H += prr[px + 16] - prr[px];
        }
    }

    // ---- Arg reduction: (max H, tie->min idx) and (min H, tie->min idx) ----
    unsigned long long kMax, kMin;
    if (tid < 226) {
        kMax = ((unsigned long long)__float_as_uint(bestMax) << 32)
             | (unsigned long long)(0xFFFFFFFFu - (unsigned)idxMax);
        kMin = ((unsigned long long)__float_as_uint(bestMin) << 32)
             | (unsigned long long)(unsigned)idxMin;
    } else {
        kMax = 0ull;
        kMin = ~0ull;
    }
    #pragma unroll
    for (int o = 16; o > 0; o >>= 1) {
        unsigned long long v;
        v = __shfl_xor_sync(0xFFFFFFFFu, kMax, o); if (v > kMax) kMax = v;
        v = __shfl_xor_sync(0xFFFFFFFFu, kMin, o); if (v < kMin) kMin = v;
    }
    const int warp = tid >> 5;
    if ((tid & 31) == 0) {
        redMaxHi[warp] = (unsigned)(kMax >> 32);
        redMaxLo[warp] = (unsigned)(kMax & 0xFFFFFFFFull);
        redMinHi[warp] = (unsigned)(kMin >> 32);
        redMinLo[warp] = (unsigned)(kMin & 0xFFFFFFFFull);
    }
    __syncthreads();

    if (tid == 0) {
        kMax = ((unsigned long long)redMaxHi[0] << 32) | redMaxLo[0];
        kMin = ((unsigned long long)redMinHi[0] << 32) | redMinLo[0];
        #pragma unroll
        for (int w = 1; w < 8; w++) {
            unsigned long long vmx = ((unsigned long long)redMaxHi[w] << 32) | redMaxLo[w];
            unsigned long long vmn = ((unsigned long long)redMinHi[w] << 32) | redMinLo[w];
            if (vmx > kMax) kMax = vmx;
            if (vmn < kMin) kMin = vmn;
        }
        const int i0 = (int)(0xFFFFFFFFu - (unsigned)(kMax & 0xFFFFFFFFull)); // class 0
        const int i1 = (int)(kMin & 0xFFFFFFFFull);                           // class 1
        const int px0 = i0 % PS, py0 = i0 / PS;
        const int px1 = i1 % PS, py1 = i1 / PS;
        int r[8] = { 2 * px0, 2 * px0 + 31, 2 * py0, 2 * py0 + 31,
                     2 * px1, 2 * px1 + 31, 2 * py1, 2 * py1 + 31 };
        float* oxy = out + (size_t)b * 8;
        #pragma unroll
        for (int i = 0; i < 8; i++) { oxy[i] = (float)r[i]; rects[i] = r[i]; }
    }
    __syncthreads();

    // ---- Phase 3: mask = union of the two rects (coalesced float4 stores) ----
    const int ox0a = rects[0], ox1a = rects[1], oy0a = rects[2], oy1a = rects[3];
    const int ox0b = rects[4], ox1b = rects[5], oy0b = rects[6], oy1b = rects[7];

    float* mout = out + (size_t)mask_off + (size_t)b * HW * HW;
    const int lane64 = tid & 63;     // x-quad index
    const int rsub   = tid >> 6;     // 0..3 (row within group of 4)
    #pragma unroll 4
    for (int it = 0; it < 64; it++) {
        const int row = it * 4 + rsub;
        const bool iny0 = (row >= oy0a) && (row <= oy1a);
        const bool iny1 = (row >= oy0b) && (row <= oy1b);
        const int x0 = lane64 * 4;
        float va[4];
        #pragma unroll
        for (int kk = 0; kk < 4; kk++) {
            const int xx = x0 + kk;
            const bool m = (iny0 && xx >= ox0a && xx <= ox1a) ||
                           (iny1 && xx >= ox0b && xx <= ox1b);
            va[kk] = m ? 1.0f : 0.0f;
        }
        float4 v; v.x = va[0]; v.y = va[1]; v.z = va[2]; v.w = va[3];
        ((float4*)mout)[row * (HW / 4) + lane64] = v;
    }
}

extern "C" void kernel_launch(void* const* d_in, const int* in_sizes, int n_in,
                              void* d_out, int out_size)
{
    const float* infeat = (const float*)d_in[0];
    const int B = in_sizes[0] / (2 * HW * HW);          // 128
    const int mask_off = out_size - B * HW * HW;        // oxy occupies the front (B*8)

    cudaFuncSetAttribute(genmask_kernel,
                         cudaFuncAttributeMaxDynamicSharedMemorySize, SMEM_BYTES);
    genmask_kernel<<<B, 256, SMEM_BYTES>>>(infeat, (float*)d_out, mask_off);
}

// round 8
// speedup vs baseline: 2.0641x; 1.2112x over previous
#include <cuda_runtime.h>

#define HW   256
#define PS   113      // (256-32)/2 + 1
#define QS   257      // padded row stride for P (prefix) table
#define PRS  129      // padded row stride for pr table
#define RED_OFF (128 * QS + 113 * PRS)
#define NT   512

// smem layout (dynamic, floats):
//   P      : 128*257   (half-relative vertical prefixes of pair-row sums)
//   pr     : 113*129   (pair-column window sums)
//   redMaxHi/Lo, redMinHi/Lo : 16 u32 each
//   rects  : 8 int
#define SMEM_FLOATS (RED_OFF + 16 * 4 + 8)
#define SMEM_BYTES  (SMEM_FLOATS * 4)

extern "C" __global__ void __launch_bounds__(NT, 1)
genmask_kernel(const float* __restrict__ infeat, float* __restrict__ out, int mask_off)
{
    extern __shared__ float smem[];
    float* P  = smem;                                   // [128][QS]
    float* pr = smem + 128 * QS;                        // [113][PRS]
    unsigned* redMaxHi = (unsigned*)(smem + RED_OFF);   // [16]
    unsigned* redMaxLo = redMaxHi + 16;
    unsigned* redMinHi = redMaxLo + 16;
    unsigned* redMinLo = redMinHi + 16;
    int*      rects    = (int*)(redMinLo + 16);         // [8]

    const int b   = blockIdx.x;
    const int tid = threadIdx.x;

    const float* base0 = infeat + (size_t)b * 2 * HW * HW;   // channel 0
    const float* base1 = base0 + HW * HW;                    // channel 1

    // ---- Phase 1: p0 = sigmoid(in0 - in1); half-relative vertical prefixes ----
    // thread t: column x = t&255, half = t>>8 owns pair-rows [64*half, 64*half+63]
    {
        const int x    = tid & 255;
        const int half = tid >> 8;
        const float* c0 = base0 + (size_t)(half * 128) * HW + x;
        const float* c1 = base1 + (size_t)(half * 128) * HW + x;
        float* Pw = P + (half * 64) * QS + x;
        float running = 0.0f;
        #pragma unroll 8
        for (int j = 0; j < 64; j++) {
            const float a0 = c0[(size_t)(2 * j) * HW];
            const float a1 = c1[(size_t)(2 * j) * HW];
            const float b0 = c0[(size_t)(2 * j + 1) * HW];
            const float b1 = c1[(size_t)(2 * j + 1) * HW];
            const float p0 = __fdividef(1.0f, 1.0f + __expf(a1 - a0));
            const float p1 = __fdividef(1.0f, 1.0f + __expf(b1 - b0));
            running += p0 + p1;
            Pw[j * QS] = running;              // relative prefix within this half
        }
    }
    __syncthreads();

    // ---- Phase 2a: pr[yo][pc] = window colsum over pair-rows [yo, yo+15], paired cols ----
    // absolute colsum = P[yo+15] - P[yo-1] (+ Ptop when the window straddles halves)
    for (int i = tid; i < PS * 128; i += NT) {
        const int yo = i >> 7;
        const int pc = i & 127;
        const int x0 = 2 * pc;
        const int hi = yo + 15;
        const float* Phi = P + hi * QS + x0;
        float v = Phi[0] + Phi[1];
        if (yo > 0) {
            const float* Plo = P + (yo - 1) * QS + x0;
            v -= Plo[0] + Plo[1];
        }
        if (hi >= 64 && yo <= 64) {            // straddle: add half-0 total
            const float* Pt = P + 63 * QS + x0;
            v += Pt[0] + Pt[1];
        }
        pr[yo * PRS + pc] = v;
    }
    __syncthreads();

    // ---- Phase 2b: (row, quarter-segment) incremental horizontal slide ----
    float bestMax = -1.0f;
    float bestMin = 1e30f;
    int   idxMax  = 0, idxMin = 0;

    if (tid < 452) {                           // 113 rows x 4 segments
        const int row = tid >> 2;
        const int seg = tid & 3;
        const int px0 = (seg == 0) ? 0 : 29 + 28 * (seg - 1);   // 0,29,57,85
        const int cnt = (seg == 0) ? 29 : 28;                   // 29+28*3 = 113
        const float* prr = pr + row * PRS;

        float H = 0.0f;
        #pragma unroll
        for (int i = 0; i < 16; i++) H += prr[px0 + i];   // window [px0 .. px0+15]

        for (int s = 0; s < cnt; s++) {
            const int px   = px0 + s;
            const int fidx = row * PS + px;
            if (H > bestMax) { bestMax = H; idxMax = fidx; }  // strict -> first index
            if (H < bestMin) { bestMin = H; idxMin = fidx; }
            if (s + 1 < cnt) H += prr[px + 16] - prr[px];
        }
    }

    // ---- Arg reduction: (max H, tie->min idx) and (min H, tie->min idx) ----
    unsigned long long kMax, kMin;
    if (tid < 452) {
        kMax = ((unsigned long long)__float_as_uint(bestMax) << 32)
             | (unsigned long long)(0xFFFFFFFFu - (unsigned)idxMax);
        kMin = ((unsigned long long)__float_as_uint(bestMin) << 32)
             | (unsigned long long)(unsigned)idxMin;
    } else {
        kMax = 0ull;
        kMin = ~0ull;
    }
    #pragma unroll
    for (int o = 16; o > 0; o >>= 1) {
        unsigned long long v;
        v = __shfl_xor_sync(0xFFFFFFFFu, kMax, o); if (v > kMax) kMax = v;
        v = __shfl_xor_sync(0xFFFFFFFFu, kMin, o); if (v < kMin) kMin = v;
    }
    const int warp = tid >> 5;
    if ((tid & 31) == 0) {
        redMaxHi[warp] = (unsigned)(kMax >> 32);
        redMaxLo[warp] = (unsigned)(kMax & 0xFFFFFFFFull);
        redMinHi[warp] = (unsigned)(kMin >> 32);
        redMinLo[warp] = (unsigned)(kMin & 0xFFFFFFFFull);
    }
    __syncthreads();

    if (tid == 0) {
        kMax = ((unsigned long long)redMaxHi[0] << 32) | redMaxLo[0];
        kMin = ((unsigned long long)redMinHi[0] << 32) | redMinLo[0];
        #pragma unroll
        for (int w = 1; w < 16; w++) {
            unsigned long long vmx = ((unsigned long long)redMaxHi[w] << 32) | redMaxLo[w];
            unsigned long long vmn = ((unsigned long long)redMinHi[w] << 32) | redMinLo[w];
            if (vmx > kMax) kMax = vmx;
            if (vmn < kMin) kMin = vmn;
        }
        const int i0 = (int)(0xFFFFFFFFu - (unsigned)(kMax & 0xFFFFFFFFull)); // class 0
        const int i1 = (int)(kMin & 0xFFFFFFFFull);                           // class 1
        const int px0 = i0 % PS, py0 = i0 / PS;
        const int px1 = i1 % PS, py1 = i1 / PS;
        int r[8] = { 2 * px0, 2 * px0 + 31, 2 * py0, 2 * py0 + 31,
                     2 * px1, 2 * px1 + 31, 2 * py1, 2 * py1 + 31 };
        float* oxy = out + (size_t)b * 8;
        #pragma unroll
        for (int i = 0; i < 8; i++) { oxy[i] = (float)r[i]; rects[i] = r[i]; }
    }
    __syncthreads();

    // ---- Phase 3: mask = union of the two rects (coalesced float4 stores) ----
    const int ox0a = rects[0], ox1a = rects[1], oy0a = rects[2], oy1a = rects[3];
    const int ox0b = rects[4], ox1b = rects[5], oy0b = rects[6], oy1b = rects[7];

    float* mout = out + (size_t)mask_off + (size_t)b * HW * HW;
    const int lane64 = tid & 63;     // x-quad index
    const int rsub   = tid >> 6;     // 0..7 (row within group of 8)
    #pragma unroll 4
    for (int it = 0; it < 32; it++) {
        const int row = it * 8 + rsub;
        const bool iny0 = (row >= oy0a) && (row <= oy1a);
        const bool iny1 = (row >= oy0b) && (row <= oy1b);
        const int x0 = lane64 * 4;
        float va[4];
        #pragma unroll
        for (int kk = 0; kk < 4; kk++) {
            const int xx = x0 + kk;
            const bool m = (iny0 && xx >= ox0a && xx <= ox1a) ||
                           (iny1 && xx >= ox0b && xx <= ox1b);
            va[kk] = m ? 1.0f : 0.0f;
        }
        float4 v; v.x = va[0]; v.y = va[1]; v.z = va[2]; v.w = va[3];
        ((float4*)mout)[row * (HW / 4) + lane64] = v;
    }
}

extern "C" void kernel_launch(void* const* d_in, const int* in_sizes, int n_in,
                              void* d_out, int out_size)
{
    const float* infeat = (const float*)d_in[0];
    const int B = in_sizes[0] / (2 * HW * HW);          // 128
    const int mask_off = out_size - B * HW * HW;        // oxy occupies the front (B*8)

    cudaFuncSetAttribute(genmask_kernel,
                         cudaFuncAttributeMaxDynamicSharedMemorySize, SMEM_BYTES);
    genmask_kernel<<<B, NT, SMEM_BYTES>>>(infeat, (float*)d_out, mask_off);
}

// round 9
// speedup vs baseline: 2.0888x; 1.0120x over previous
#include <cuda_runtime.h>

#define HW   256
#define PS   113      // (256-32)/2 + 1
#define QS   257      // padded row stride for P (prefix) table
#define PRS  129      // padded row stride for pr table
#define RED_OFF (128 * QS + 113 * PRS)
#define NT   1024

// smem layout (dynamic, floats):
//   P      : 128*257   (quarter-relative vertical prefixes of pair-row sums)
//   pr     : 113*129   (pair-column window sums)
//   redMaxHi/Lo, redMinHi/Lo : 32 u32 each
//   rects  : 8 int
#define SMEM_FLOATS (RED_OFF + 32 * 4 + 8)
#define SMEM_BYTES  (SMEM_FLOATS * 4)

extern "C" __global__ void __launch_bounds__(NT, 1)
genmask_kernel(const float* __restrict__ infeat, float* __restrict__ out, int mask_off)
{
    extern __shared__ float smem[];
    float* P  = smem;                                   // [128][QS]
    float* pr = smem + 128 * QS;                        // [113][PRS]
    unsigned* redMaxHi = (unsigned*)(smem + RED_OFF);   // [32]
    unsigned* redMaxLo = redMaxHi + 32;
    unsigned* redMinHi = redMaxLo + 32;
    unsigned* redMinLo = redMinHi + 32;
    int*      rects    = (int*)(redMinLo + 32);         // [8]

    const int b   = blockIdx.x;
    const int tid = threadIdx.x;

    const float* base0 = infeat + (size_t)b * 2 * HW * HW;   // channel 0
    const float* base1 = base0 + HW * HW;                    // channel 1

    // ---- Phase 1: p0 = sigmoid(in0 - in1); quarter-relative vertical prefixes ----
    // thread t: column x = t&255, quarter q = t>>8 owns pair-rows [32q, 32q+31]
    {
        const int x = tid & 255;
        const int q = tid >> 8;
        const float* c0 = base0 + (size_t)(q * 64) * HW + x;
        const float* c1 = base1 + (size_t)(q * 64) * HW + x;
        float* Pw = P + (q * 32) * QS + x;
        float running = 0.0f;
        #pragma unroll 8
        for (int j = 0; j < 32; j++) {
            const float a0 = c0[(size_t)(2 * j) * HW];
            const float a1 = c1[(size_t)(2 * j) * HW];
            const float b0 = c0[(size_t)(2 * j + 1) * HW];
            const float b1 = c1[(size_t)(2 * j + 1) * HW];
            const float p0 = __fdividef(1.0f, 1.0f + __expf(a1 - a0));
            const float p1 = __fdividef(1.0f, 1.0f + __expf(b1 - b0));
            running += p0 + p1;
            Pw[j * QS] = running;              // relative prefix within this quarter
        }
    }
    __syncthreads();

    // ---- Phase 2a: pr[yo][pc] = window colsum over pair-rows [yo, yo+15], paired cols ----
    // 16-deep window spans at most one quarter boundary:
    //   v = P[hi] - P[yo-1] + (straddle ? Ptot[q_hi - 1] : 0)
    for (int i = tid; i < PS * 128; i += NT) {
        const int yo = i >> 7;
        const int pc = i & 127;
        const int x0 = 2 * pc;
        const int hi = yo + 15;
        const int qhi = hi >> 5;
        const float* Phi = P + hi * QS + x0;
        float v = Phi[0] + Phi[1];
        if (yo > 0) {
            const float* Plo = P + (yo - 1) * QS + x0;
            v -= Plo[0] + Plo[1];
            if (((yo - 1) >> 5) != qhi) {      // straddle (incl. exact-boundary cancel)
                const float* Pt = P + ((qhi << 5) - 1) * QS + x0;
                v += Pt[0] + Pt[1];
            }
        }
        pr[yo * PRS + pc] = v;
    }
    __syncthreads();

    // ---- Phase 2b: (row, eighth-segment) incremental horizontal slide ----
    float bestMax = -1.0f;
    float bestMin = 1e30f;
    int   idxMax  = 0, idxMin = 0;

    if (tid < 904) {                           // 113 rows x 8 segments
        const int row = tid >> 3;
        const int seg = tid & 7;
        const int px0 = (seg == 0) ? 0 : 15 + 14 * (seg - 1);   // 0,15,29,...,99
        const int cnt = (seg == 0) ? 15 : 14;                   // 15 + 14*7 = 113
        const float* prr = pr + row * PRS;

        float H = 0.0f;
        #pragma unroll
        for (int i = 0; i < 16; i++) H += prr[px0 + i];   // window [px0 .. px0+15]

        for (int s = 0; s < cnt; s++) {
            const int px   = px0 + s;
            const int fidx = row * PS + px;
            if (H > bestMax) { bestMax = H; idxMax = fidx; }  // strict -> first index
            if (H < bestMin) { bestMin = H; idxMin = fidx; }
            if (s + 1 < cnt) H += prr[px + 16] - prr[px];
        }
    }

    // ---- Arg reduction: (max H, tie->min idx) and (min H, tie->min idx) ----
    unsigned long long kMax, kMin;
    if (tid < 904) {
        kMax = ((unsigned long long)__float_as_uint(bestMax) << 32)
             | (unsigned long long)(0xFFFFFFFFu - (unsigned)idxMax);
        kMin = ((unsigned long long)__float_as_uint(bestMin) << 32)
             | (unsigned long long)(unsigned)idxMin;
    } else {
        kMax = 0ull;
        kMin = ~0ull;
    }
    #pragma unroll
    for (int o = 16; o > 0; o >>= 1) {
        unsigned long long v;
        v = __shfl_xor_sync(0xFFFFFFFFu, kMax, o); if (v > kMax) kMax = v;
        v = __shfl_xor_sync(0xFFFFFFFFu, kMin, o); if (v < kMin) kMin = v;
    }
    const int warp = tid >> 5;
    if ((tid & 31) == 0) {
        redMaxHi[warp] = (unsigned)(kMax >> 32);
        redMaxLo[warp] = (unsigned)(kMax & 0xFFFFFFFFull);
        redMinHi[warp] = (unsigned)(kMin >> 32);
        redMinLo[warp] = (unsigned)(kMin & 0xFFFFFFFFull);
    }
    __syncthreads();

    if (tid == 0) {
        kMax = ((unsigned long long)redMaxHi[0] << 32) | redMaxLo[0];
        kMin = ((unsigned long long)redMinHi[0] << 32) | redMinLo[0];
        #pragma unroll
        for (int w = 1; w < 32; w++) {
            unsigned long long vmx = ((unsigned long long)redMaxHi[w] << 32) | redMaxLo[w];
            unsigned long long vmn = ((unsigned long long)redMinHi[w] << 32) | redMinLo[w];
            if (vmx > kMax) kMax = vmx;
            if (vmn < kMin) kMin = vmn;
        }
        const int i0 = (int)(0xFFFFFFFFu - (unsigned)(kMax & 0xFFFFFFFFull)); // class 0
        const int i1 = (int)(kMin & 0xFFFFFFFFull);                           // class 1
        const int px0 = i0 % PS, py0 = i0 / PS;
        const int px1 = i1 % PS, py1 = i1 / PS;
        int r[8] = { 2 * px0, 2 * px0 + 31, 2 * py0, 2 * py0 + 31,
                     2 * px1, 2 * px1 + 31, 2 * py1, 2 * py1 + 31 };
        float* oxy = out + (size_t)b * 8;
        #pragma unroll
        for (int i = 0; i < 8; i++) { oxy[i] = (float)r[i]; rects[i] = r[i]; }
    }
    __syncthreads();

    // ---- Phase 3: mask = union of the two rects (coalesced float4 stores) ----
    const int ox0a = rects[0], ox1a = rects[1], oy0a = rects[2], oy1a = rects[3];
    const int ox0b = rects[4], ox1b = rects[5], oy0b = rects[6], oy1b = rects[7];

    float* mout = out + (size_t)mask_off + (size_t)b * HW * HW;
    const int lane64 = tid & 63;     // x-quad index
    const int rsub   = tid >> 6;     // 0..15 (row within group of 16)
    #pragma unroll 4
    for (int it = 0; it < 16; it++) {
        const int row = it * 16 + rsub;
        const bool iny0 = (row >= oy0a) && (row <= oy1a);
        const bool iny1 = (row >= oy0b) && (row <= oy1b);
        const int x0 = lane64 * 4;
        float va[4];
        #pragma unroll
        for (int kk = 0; kk < 4; kk++) {
            const int xx = x0 + kk;
            const bool m = (iny0 && xx >= ox0a && xx <= ox1a) ||
                           (iny1 && xx >= ox0b && xx <= ox1b);
            va[kk] = m ? 1.0f : 0.0f;
        }
        float4 v; v.x = va[0]; v.y = va[1]; v.z = va[2]; v.w = va[3];
        ((float4*)mout)[row * (HW / 4) + lane64] = v;
    }
}

extern "C" void kernel_launch(void* const* d_in, const int* in_sizes, int n_in,
                              void* d_out, int out_size)
{
    const float* infeat = (const float*)d_in[0];
    const int B = in_sizes[0] / (2 * HW * HW);          // 128
    const int mask_off = out_size - B * HW * HW;        // oxy occupies the front (B*8)

    cudaFuncSetAttribute(genmask_kernel,
                         cudaFuncAttributeMaxDynamicSharedMemorySize, SMEM_BYTES);
    genmask_kernel<<<B, NT, SMEM_BYTES>>>(infeat, (float*)d_out, mask_off);
}

// round 10
// speedup vs baseline: 2.4000x; 1.1490x over previous
#include <cuda_runtime.h>

#define HW   256
#define PS   113      // (256-32)/2 + 1
#define QS   257      // padded row stride for P (prefix) table
#define PRS  129      // padded row stride for pr table
#define RED_OFF (128 * QS + 113 * PRS)
#define NT   1024

// smem layout (dynamic, floats):
//   P      : 128*257   (quarter-relative vertical prefixes of pair-row sums)
//   pr     : 113*129   (pair-column window sums)
//   redMaxHi/Lo, redMinHi/Lo : 32 u32 each
//   rects  : 8 int
#define SMEM_FLOATS (RED_OFF + 32 * 4 + 8)
#define SMEM_BYTES  (SMEM_FLOATS * 4)

__device__ __forceinline__ void st_stream_f32(float* p, float v) {
    asm volatile("st.global.cs.f32 [%0], %1;" :: "l"(p), "f"(v) : "memory");
}
__device__ __forceinline__ void st_stream_f4(float4* p, float4 v) {
    asm volatile("st.global.cs.v4.f32 [%0], {%1, %2, %3, %4};"
                 :: "l"(p), "f"(v.x), "f"(v.y), "f"(v.z), "f"(v.w) : "memory");
}

extern "C" __global__ void __launch_bounds__(NT, 1)
genmask_kernel(const float* __restrict__ infeat, float* __restrict__ out, int mask_off)
{
    extern __shared__ float smem[];
    float* P  = smem;                                   // [128][QS]
    float* pr = smem + 128 * QS;                        // [113][PRS]
    unsigned* redMaxHi = (unsigned*)(smem + RED_OFF);   // [32]
    unsigned* redMaxLo = redMaxHi + 32;
    unsigned* redMinHi = redMaxLo + 32;
    unsigned* redMinLo = redMinHi + 32;
    int*      rects    = (int*)(redMinLo + 32);         // [8]

    const int b   = blockIdx.x;
    const int tid = threadIdx.x;

    const float* base0 = infeat + (size_t)b * 2 * HW * HW;   // channel 0
    const float* base1 = base0 + HW * HW;                    // channel 1

    // ---- Phase 1: p0 = sigmoid(in0 - in1); quarter-relative vertical prefixes ----
    // thread t: column x = t&255, quarter q = t>>8 owns pair-rows [32q, 32q+31]
    {
        const int x = tid & 255;
        const int q = tid >> 8;
        const float* c0 = base0 + (size_t)(q * 64) * HW + x;
        const float* c1 = base1 + (size_t)(q * 64) * HW + x;
        float* Pw = P + (q * 32) * QS + x;
        float running = 0.0f;
        #pragma unroll 8
        for (int j = 0; j < 32; j++) {
            const float a0 = c0[(size_t)(2 * j) * HW];
            const float a1 = c1[(size_t)(2 * j) * HW];
            const float b0 = c0[(size_t)(2 * j + 1) * HW];
            const float b1 = c1[(size_t)(2 * j + 1) * HW];
            const float p0 = __fdividef(1.0f, 1.0f + __expf(a1 - a0));
            const float p1 = __fdividef(1.0f, 1.0f + __expf(b1 - b0));
            running += p0 + p1;
            Pw[j * QS] = running;              // relative prefix within this quarter
        }
    }
    __syncthreads();

    // ---- Phase 2a: pr[yo][pc] = window colsum over pair-rows [yo, yo+15], paired cols ----
    // 16-deep window spans at most one quarter boundary:
    //   v = P[hi] - P[yo-1] + (straddle ? Ptot[q_hi - 1] : 0)
    for (int i = tid; i < PS * 128; i += NT) {
        const int yo = i >> 7;
        const int pc = i & 127;
        const int x0 = 2 * pc;
        const int hi = yo + 15;
        const int qhi = hi >> 5;
        const float* Phi = P + hi * QS + x0;
        float v = Phi[0] + Phi[1];
        if (yo > 0) {
            const float* Plo = P + (yo - 1) * QS + x0;
            v -= Plo[0] + Plo[1];
            if (((yo - 1) >> 5) != qhi) {      // straddle (incl. exact-boundary cancel)
                const float* Pt = P + ((qhi << 5) - 1) * QS + x0;
                v += Pt[0] + Pt[1];
            }
        }
        pr[yo * PRS + pc] = v;
    }
    __syncthreads();

    // ---- Phase 2b: (row, eighth-segment) incremental horizontal slide ----
    float bestMax = -1.0f;
    float bestMin = 1e30f;
    int   idxMax  = 0, idxMin = 0;

    if (tid < 904) {                           // 113 rows x 8 segments
        const int row = tid >> 3;
        const int seg = tid & 7;
        const int px0 = (seg == 0) ? 0 : 15 + 14 * (seg - 1);   // 0,15,29,...,99
        const int cnt = (seg == 0) ? 15 : 14;                   // 15 + 14*7 = 113
        const float* prr = pr + row * PRS;

        float H = 0.0f;
        #pragma unroll
        for (int i = 0; i < 16; i++) H += prr[px0 + i];   // window [px0 .. px0+15]

        for (int s = 0; s < cnt; s++) {
            const int px   = px0 + s;
            const int fidx = row * PS + px;
            if (H > bestMax) { bestMax = H; idxMax = fidx; }  // strict -> first index
            if (H < bestMin) { bestMin = H; idxMin = fidx; }
            if (s + 1 < cnt) H += prr[px + 16] - prr[px];
        }
    }

    // ---- Arg reduction: (max H, tie->min idx) and (min H, tie->min idx) ----
    unsigned long long kMax, kMin;
    if (tid < 904) {
        kMax = ((unsigned long long)__float_as_uint(bestMax) << 32)
             | (unsigned long long)(0xFFFFFFFFu - (unsigned)idxMax);
        kMin = ((unsigned long long)__float_as_uint(bestMin) << 32)
             | (unsigned long long)(unsigned)idxMin;
    } else {
        kMax = 0ull;
        kMin = ~0ull;
    }
    #pragma unroll
    for (int o = 16; o > 0; o >>= 1) {
        unsigned long long v;
        v = __shfl_xor_sync(0xFFFFFFFFu, kMax, o); if (v > kMax) kMax = v;
        v = __shfl_xor_sync(0xFFFFFFFFu, kMin, o); if (v < kMin) kMin = v;
    }
    const int warp = tid >> 5;
    if ((tid & 31) == 0) {
        redMaxHi[warp] = (unsigned)(kMax >> 32);
        redMaxLo[warp] = (unsigned)(kMax & 0xFFFFFFFFull);
        redMinHi[warp] = (unsigned)(kMin >> 32);
        redMinLo[warp] = (unsigned)(kMin & 0xFFFFFFFFull);
    }
    __syncthreads();

    if (tid == 0) {
        kMax = ((unsigned long long)redMaxHi[0] << 32) | redMaxLo[0];
        kMin = ((unsigned long long)redMinHi[0] << 32) | redMinLo[0];
        #pragma unroll
        for (int w = 1; w < 32; w++) {
            unsigned long long vmx = ((unsigned long long)redMaxHi[w] << 32) | redMaxLo[w];
            unsigned long long vmn = ((unsigned long long)redMinHi[w] << 32) | redMinLo[w];
            if (vmx > kMax) kMax = vmx;
            if (vmn < kMin) kMin = vmn;
        }
        const int i0 = (int)(0xFFFFFFFFu - (unsigned)(kMax & 0xFFFFFFFFull)); // class 0
        const int i1 = (int)(kMin & 0xFFFFFFFFull);                           // class 1
        const int px0 = i0 % PS, py0 = i0 / PS;
        const int px1 = i1 % PS, py1 = i1 / PS;
        int r[8] = { 2 * px0, 2 * px0 + 31, 2 * py0, 2 * py0 + 31,
                     2 * px1, 2 * px1 + 31, 2 * py1, 2 * py1 + 31 };
        float* oxy = out + (size_t)b * 8;
        #pragma unroll
        for (int i = 0; i < 8; i++) { st_stream_f32(oxy + i, (float)r[i]); rects[i] = r[i]; }
    }
    __syncthreads();

    // ---- Phase 3: mask = union of the two rects (streaming float4 stores) ----
    const int ox0a = rects[0], ox1a = rects[1], oy0a = rects[2], oy1a = rects[3];
    const int ox0b = rects[4], ox1b = rects[5], oy0b = rects[6], oy1b = rects[7];

    float* mout = out + (size_t)mask_off + (size_t)b * HW * HW;
    const int lane64 = tid & 63;     // x-quad index
    const int rsub   = tid >> 6;     // 0..15 (row within group of 16)
    #pragma unroll 4
    for (int it = 0; it < 16; it++) {
        const int row = it * 16 + rsub;
        const bool iny0 = (row >= oy0a) && (row <= oy1a);
        const bool iny1 = (row >= oy0b) && (row <= oy1b);
        const int x0 = lane64 * 4;
        float va[4];
        #pragma unroll
        for (int kk = 0; kk < 4; kk++) {
            const int xx = x0 + kk;
            const bool m = (iny0 && xx >= ox0a && xx <= ox1a) ||
                           (iny1 && xx >= ox0b && xx <= ox1b);
            va[kk] = m ? 1.0f : 0.0f;
        }
        float4 v; v.x = va[0]; v.y = va[1]; v.z = va[2]; v.w = va[3];
        st_stream_f4((float4*)mout + row * (HW / 4) + lane64, v);
    }
}

extern "C" void kernel_launch(void* const* d_in, const int* in_sizes, int n_in,
                              void* d_out, int out_size)
{
    const float* infeat = (const float*)d_in[0];
    const int B = in_sizes[0] / (2 * HW * HW);          // 128
    const int mask_off = out_size - B * HW * HW;        // oxy occupies the front (B*8)

    cudaFuncSetAttribute(genmask_kernel,
                         cudaFuncAttributeMaxDynamicSharedMemorySize, SMEM_BYTES);
    genmask_kernel<<<B, NT, SMEM_BYTES>>>(infeat, (float*)d_out, mask_off);
}

// round 11
// speedup vs baseline: 2.7188x; 1.1328x over previous
#include <cuda_runtime.h>

#define HW   256
#define PS   113      // (256-32)/2 + 1
#define PP   129      // padded row stride for P (pair-column prefix) table
#define PRS  129      // padded row stride for pr table
#define RED_OFF (128 * PP + 113 * PRS)
#define NT   1024

// smem layout (dynamic, floats):
//   P      : 128*129   (slice-relative vertical prefixes of 2x2-summed sigmoid, per pair-col)
//   pr     : 113*129   (pair-column window sums)
//   redMaxHi/Lo, redMinHi/Lo : 32 u32 each
//   rects  : 8 int
#define SMEM_FLOATS (RED_OFF + 32 * 4 + 8)
#define SMEM_BYTES  (SMEM_FLOATS * 4)

__device__ __forceinline__ void st_stream_f32(float* p, float v) {
    asm volatile("st.global.cs.f32 [%0], %1;" :: "l"(p), "f"(v) : "memory");
}
__device__ __forceinline__ void st_stream_f4(float4* p, float4 v) {
    asm volatile("st.global.cs.v4.f32 [%0], {%1, %2, %3, %4};"
                 :: "l"(p), "f"(v.x), "f"(v.y), "f"(v.z), "f"(v.w) : "memory");
}

__device__ __forceinline__ float sigm(float d) {       // 1/(1+e^{-d})
    return __fdividef(1.0f, 1.0f + __expf(-d));
}

extern "C" __global__ void __launch_bounds__(NT, 1)
genmask_kernel(const float* __restrict__ infeat, float* __restrict__ out, int mask_off)
{
    extern __shared__ float smem[];
    float* P  = smem;                                   // [128][PP]
    float* pr = smem + 128 * PP;                        // [113][PRS]
    unsigned* redMaxHi = (unsigned*)(smem + RED_OFF);   // [32]
    unsigned* redMaxLo = redMaxHi + 32;
    unsigned* redMinHi = redMaxLo + 32;
    unsigned* redMinLo = redMinHi + 32;
    int*      rects    = (int*)(redMinLo + 32);         // [8]

    const int b   = blockIdx.x;
    const int tid = threadIdx.x;

    const float* base0 = infeat + (size_t)b * 2 * HW * HW;   // channel 0
    const float* base1 = base0 + HW * HW;                    // channel 1

    // ---- Phase 1: 2x2-summed sigmoid prefix per pair-column ----
    // thread t: pair-column pc = t&127 (cols 2pc,2pc+1), slice s = t>>7 owns
    // pair-rows [16s .. 16s+15]; stores slice-relative prefixes.
    {
        const int pc = tid & 127;
        const int s  = tid >> 7;
        const float2* c0 = (const float2*)(base0 + (size_t)(32 * s) * HW) + pc;
        const float2* c1 = (const float2*)(base1 + (size_t)(32 * s) * HW) + pc;
        float* Pw = P + (16 * s) * PP + pc;
        float running = 0.0f;
        #pragma unroll 4
        for (int j = 0; j < 16; j++) {
            const float2 a0 = c0[(size_t)(2 * j) * (HW / 2)];
            const float2 a1 = c1[(size_t)(2 * j) * (HW / 2)];
            const float2 b0 = c0[(size_t)(2 * j + 1) * (HW / 2)];
            const float2 b1 = c1[(size_t)(2 * j + 1) * (HW / 2)];
            running += sigm(a0.x - a1.x) + sigm(a0.y - a1.y)
                     + sigm(b0.x - b1.x) + sigm(b0.y - b1.y);
            Pw[j * PP] = running;              // relative prefix within this slice
        }
    }
    __syncthreads();

    // ---- Phase 2a: pr[yo][pc] = window sum over pair-rows [yo, yo+15] ----
    // 16-deep window spans at most one 16-row slice boundary:
    //   v = P[hi] - P[yo-1] + (straddle ? Ptot[slice(hi)-1] : 0)
    for (int i = tid; i < PS * 128; i += NT) {
        const int yo = i >> 7;
        const int pc = i & 127;
        const int hi = yo + 15;
        float v = P[hi * PP + pc];
        if (yo > 0) {
            v -= P[(yo - 1) * PP + pc];
            if (((yo - 1) >> 4) != (hi >> 4)) {    // straddle (boundary edge cancels)
                v += P[(((hi >> 4) << 4) - 1) * PP + pc];
            }
        }
        pr[yo * PRS + pc] = v;
    }
    __syncthreads();

    // ---- Phase 2b: (row, eighth-segment) incremental horizontal slide ----
    float bestMax = -1.0f;
    float bestMin = 1e30f;
    int   idxMax  = 0, idxMin = 0;

    if (tid < 904) {                           // 113 rows x 8 segments
        const int row = tid >> 3;
        const int seg = tid & 7;
        const int px0 = (seg == 0) ? 0 : 15 + 14 * (seg - 1);   // 0,15,29,...,99
        const int cnt = (seg == 0) ? 15 : 14;                   // 15 + 14*7 = 113
        const float* prr = pr + row * PRS;

        float H = 0.0f;
        #pragma unroll
        for (int i = 0; i < 16; i++) H += prr[px0 + i];   // window [px0 .. px0+15]

        for (int s = 0; s < cnt; s++) {
            const int px   = px0 + s;
            const int fidx = row * PS + px;
            if (H > bestMax) { bestMax = H; idxMax = fidx; }  // strict -> first index
            if (H < bestMin) { bestMin = H; idxMin = fidx; }
            if (s + 1 < cnt) H += prr[px + 16] - prr[px];
        }
    }

    // ---- Arg reduction: (max H, tie->min idx) and (min H, tie->min idx) ----
    unsigned long long kMax, kMin;
    if (tid < 904) {
        kMax = ((unsigned long long)__float_as_uint(bestMax) << 32)
             | (unsigned long long)(0xFFFFFFFFu - (unsigned)idxMax);
        kMin = ((unsigned long long)__float_as_uint(bestMin) << 32)
             | (unsigned long long)(unsigned)idxMin;
    } else {
        kMax = 0ull;
        kMin = ~0ull;
    }
    #pragma unroll
    for (int o = 16; o > 0; o >>= 1) {
        unsigned long long v;
        v = __shfl_xor_sync(0xFFFFFFFFu, kMax, o); if (v > kMax) kMax = v;
        v = __shfl_xor_sync(0xFFFFFFFFu, kMin, o); if (v < kMin) kMin = v;
    }
    const int warp = tid >> 5;
    if ((tid & 31) == 0) {
        redMaxHi[warp] = (unsigned)(kMax >> 32);
        redMaxLo[warp] = (unsigned)(kMax & 0xFFFFFFFFull);
        redMinHi[warp] = (unsigned)(kMin >> 32);
        redMinLo[warp] = (unsigned)(kMin & 0xFFFFFFFFull);
    }
    __syncthreads();

    if (tid == 0) {
        kMax = ((unsigned long long)redMaxHi[0] << 32) | redMaxLo[0];
        kMin = ((unsigned long long)redMinHi[0] << 32) | redMinLo[0];
        #pragma unroll
        for (int w = 1; w < 32; w++) {
            unsigned long long vmx = ((unsigned long long)redMaxHi[w] << 32) | redMaxLo[w];
            unsigned long long vmn = ((unsigned long long)redMinHi[w] << 32) | redMinLo[w];
            if (vmx > kMax) kMax = vmx;
            if (vmn < kMin) kMin = vmn;
        }
        const int i0 = (int)(0xFFFFFFFFu - (unsigned)(kMax & 0xFFFFFFFFull)); // class 0
        const int i1 = (int)(kMin & 0xFFFFFFFFull);                           // class 1
        const int px0 = i0 % PS, py0 = i0 / PS;
        const int px1 = i1 % PS, py1 = i1 / PS;
        int r[8] = { 2 * px0, 2 * px0 + 31, 2 * py0, 2 * py0 + 31,
                     2 * px1, 2 * px1 + 31, 2 * py1, 2 * py1 + 31 };
        float* oxy = out + (size_t)b * 8;
        #pragma unroll
        for (int i = 0; i < 8; i++) { st_stream_f32(oxy + i, (float)r[i]); rects[i] = r[i]; }
    }
    __syncthreads();

    // ---- Phase 3: mask = union of the two rects (streaming float4 stores) ----
    const int ox0a = rects[0], ox1a = rects[1], oy0a = rects[2], oy1a = rects[3];
    const int ox0b = rects[4], ox1b = rects[5], oy0b = rects[6], oy1b = rects[7];

    float* mout = out + (size_t)mask_off + (size_t)b * HW * HW;
    const int lane64 = tid & 63;     // x-quad index
    const int rsub   = tid >> 6;     // 0..15 (row within group of 16)
    #pragma unroll 4
    for (int it = 0; it < 16; it++) {
        const int row = it * 16 + rsub;
        const bool iny0 = (row >= oy0a) && (row <= oy1a);
        const bool iny1 = (row >= oy0b) && (row <= oy1b);
        const int x0 = lane64 * 4;
        float va[4];
        #pragma unroll
        for (int kk = 0; kk < 4; kk++) {
            const int xx = x0 + kk;
            const bool m = (iny0 && xx >= ox0a && xx <= ox1a) ||
                           (iny1 && xx >= ox0b && xx <= ox1b);
            va[kk] = m ? 1.0f : 0.0f;
        }
        float4 v; v.x = va[0]; v.y = va[1]; v.z = va[2]; v.w = va[3];
        st_stream_f4((float4*)mout + row * (HW / 4) + lane64, v);
    }
}

extern "C" void kernel_launch(void* const* d_in, const int* in_sizes, int n_in,
                              void* d_out, int out_size)
{
    const float* infeat = (const float*)d_in[0];
    const int B = in_sizes[0] / (2 * HW * HW);          // 128
    const int mask_off = out_size - B * HW * HW;        // oxy occupies the front (B*8)

    cudaFuncSetAttribute(genmask_kernel,
                         cudaFuncAttributeMaxDynamicSharedMemorySize, SMEM_BYTES);
    genmask_kernel<<<B, NT, SMEM_BYTES>>>(infeat, (float*)d_out, mask_off);
}